// round 13
// baseline (speedup 1.0000x reference)
#include <cuda_runtime.h>
#include <cuda_fp16.h>
#include <cstdint>
#include <cstddef>

#define N_NODES 100000
#define N_EDGES 3200000
#define IN_DIM  256
#define HID     128
#define OUT_DIM 2
#define BN_EPS  1e-5f

#define SC_BLOCKS 100
#define SC_THREADS 256
#define SC_PER 4   // 100*256*4 = 102400 >= N_NODES

#define GBM 128
#define GBK 32
#define A_S 36
#define B_S 132
#define NBLK_GEMM ((N_NODES + GBM - 1) / GBM)          // 782
#define NBLK_EDGE ((N_EDGES / 8 + 255) / 256)          // 1563

// ---------------- scratch (static device globals; no runtime alloc) --------
__device__ __align__(16) float  g_dinv[N_NODES];
__device__ __align__(16) __half g_h1s[(size_t)N_NODES * HID];   // fp16 h1 (unscaled)
__device__ __align__(16) __half g_hpre[(size_t)N_NODES * HID];  // fp16 pre-BN h
__device__ __align__(16) float  g_h2s[N_NODES * OUT_DIM];
__device__ __align__(16) float  g_W1s[IN_DIM * HID];            // tf32-rounded W1*sig(fi)
__device__ __align__(16) float  g_sums[HID];
__device__ __align__(16) float  g_sumsq[HID];
// CSR by destination
__device__ __align__(16) int    g_cnt[N_NODES];
__device__ __align__(16) int    g_off[N_NODES + 1];
__device__ __align__(16) int    g_cursor[N_NODES];
__device__ __align__(16) int    g_csr_row[N_EDGES];
// fused-scan scratch
__device__ __align__(16) int    g_bpart[SC_BLOCKS];
__device__ int                  g_arrive;

// ---------------- helpers ---------------------------------------------------
__device__ __forceinline__ float to_tf32(float x) {
    uint32_t u;
    asm("cvt.rna.tf32.f32 %0, %1;" : "=r"(u) : "f"(x));
    return __uint_as_float(u);
}

__device__ __forceinline__ void mma_tf32(float* c,
                                         uint32_t a0, uint32_t a1, uint32_t a2, uint32_t a3,
                                         uint32_t b0, uint32_t b1) {
    asm volatile(
        "mma.sync.aligned.m16n8k8.row.col.f32.tf32.tf32.f32 "
        "{%0,%1,%2,%3}, {%4,%5,%6,%7}, {%8,%9}, {%0,%1,%2,%3};"
        : "+f"(c[0]), "+f"(c[1]), "+f"(c[2]), "+f"(c[3])
        : "r"(a0), "r"(a1), "r"(a2), "r"(a3), "r"(b0), "r"(b1));
}

__device__ __forceinline__ uint32_t smem_addr_u32(const void* p) {
    return (uint32_t)__cvta_generic_to_shared(p);
}

__device__ __forceinline__ void cp16(uint32_t dst, const void* src, uint32_t sz) {
    asm volatile("cp.async.cg.shared.global [%0], [%1], 16, %2;"
                 :: "r"(dst), "l"(src), "r"(sz));
}

// ---------------- K0: prep (fold sigmoid into W1 -> tf32, zero counters) ----
__global__ void k_prep(const float* __restrict__ W1, const float* __restrict__ fi) {
    int i = blockIdx.x * blockDim.x + threadIdx.x;
    if (i < IN_DIM * HID) {
        int k = i / HID;
        float s = 1.0f / (1.0f + __expf(-fi[k]));
        g_W1s[i] = to_tf32(W1[i] * s);
    }
    if (i < N_NODES) g_cnt[i] = 0;
    if (i < HID) { g_sums[i] = 0.0f; g_sumsq[i] = 0.0f; }
    if (i == 0) g_arrive = 0;
}

// ---------------- K_GEMM: cp.async double-buffered tf32 GEMM, 1 CTA/SM ------
__global__ __launch_bounds__(256, 1) void k_gemm1(const float* __restrict__ x) {
    __shared__ float As[2][GBM * A_S];
    __shared__ float Bs[2][GBK * B_S];
    const int m0   = blockIdx.x * GBM;
    const int tid  = threadIdx.x;
    const int lane = tid & 31;
    const int wid  = tid >> 5;
    const int wm   = wid >> 2;
    const int wn   = wid & 3;
    const int grp  = lane >> 2;
    const int tg   = lane & 3;

    float acc[4][4][4];
    #pragma unroll
    for (int im = 0; im < 4; ++im)
        #pragma unroll
        for (int in = 0; in < 4; ++in)
            #pragma unroll
            for (int q = 0; q < 4; ++q) acc[im][in][q] = 0.f;

    // issue async loads of tile kt into buffer bf
    auto issue_tile = [&](int kt, int bf) {
        int k0 = kt * GBK;
        // A: 128 rows x 32 cols = 1024 x 16B, 4 per thread (zfill OOB rows)
        #pragma unroll
        for (int p = 0; p < 4; ++p) {
            int slot = tid + p * 256;
            int r = slot >> 3;           // 0..127
            int q = slot & 7;            // 16B chunk in k
            int gm = m0 + r;
            uint32_t dst = smem_addr_u32(&As[bf][r * A_S + q * 4]);
            uint32_t sz = (gm < N_NODES) ? 16u : 0u;
            cp16(dst, x + (size_t)gm * IN_DIM + k0 + q * 4, sz);
        }
        // B: 32 rows x 128 cols = 1024 x 16B, 4 per thread
        #pragma unroll
        for (int p = 0; p < 4; ++p) {
            int slot = tid + p * 256;
            int r = slot >> 5;           // 0..31
            int c = slot & 31;           // 16B chunk in n
            uint32_t dst = smem_addr_u32(&Bs[bf][r * B_S + c * 4]);
            cp16(dst, g_W1s + (size_t)(k0 + r) * HID + c * 4, 16u);
        }
        asm volatile("cp.async.commit_group;" ::: "memory");
    };

    const int NT = IN_DIM / GBK;   // 8
    issue_tile(0, 0);
    for (int t = 0; t < NT; ++t) {
        int bf = t & 1;
        if (t + 1 < NT) issue_tile(t + 1, bf ^ 1);
        if (t + 1 < NT)
            asm volatile("cp.async.wait_group 1;" ::: "memory");
        else
            asm volatile("cp.async.wait_group 0;" ::: "memory");
        __syncthreads();

        #pragma unroll
        for (int ks = 0; ks < GBK; ks += 8) {
            uint32_t a[4][4], b[4][2];
            #pragma unroll
            for (int im = 0; im < 4; ++im) {
                int mb = wm * 64 + im * 16;
                const float* pa = &As[bf][(mb + grp) * A_S + ks + tg];
                a[im][0] = __float_as_uint(pa[0]);
                a[im][1] = __float_as_uint(pa[8 * A_S]);
                a[im][2] = __float_as_uint(pa[4]);
                a[im][3] = __float_as_uint(pa[8 * A_S + 4]);
            }
            #pragma unroll
            for (int in = 0; in < 4; ++in) {
                int nb = wn * 32 + in * 8 + grp;
                const float* pb = &Bs[bf][(ks + tg) * B_S + nb];
                b[in][0] = __float_as_uint(pb[0]);
                b[in][1] = __float_as_uint(pb[4 * B_S]);
            }
            #pragma unroll
            for (int im = 0; im < 4; ++im)
                #pragma unroll
                for (int in = 0; in < 4; ++in)
                    mma_tf32(acc[im][in], a[im][0], a[im][1], a[im][2], a[im][3],
                             b[in][0], b[in][1]);
        }
        __syncthreads();   // protect buffer bf before it is re-filled at t+2
    }

    #pragma unroll
    for (int im = 0; im < 4; ++im) {
        int r0 = m0 + wm * 64 + im * 16 + grp;
        int r1 = r0 + 8;
        #pragma unroll
        for (int in = 0; in < 4; ++in) {
            int col = wn * 32 + in * 8 + tg * 2;
            if (r0 < N_NODES) {
                __half2 h = __floats2half2_rn(acc[im][in][0], acc[im][in][1]);
                *(__half2*)(g_h1s + (size_t)r0 * HID + col) = h;
            }
            if (r1 < N_NODES) {
                __half2 h = __floats2half2_rn(acc[im][in][2], acc[im][in][3]);
                *(__half2*)(g_h1s + (size_t)r1 * HID + col) = h;
            }
        }
    }
}

// ---------------- K1: in-degree histogram (standalone, high occupancy) ------
__global__ void k_deg(const int* __restrict__ ei) {
    int t = blockIdx.x * blockDim.x + threadIdx.x;
    int e8 = t * 8;
    if (e8 >= N_EDGES) return;
    int4 c0 = *(const int4*)(ei + N_EDGES + e8);
    int4 c1 = *(const int4*)(ei + N_EDGES + e8 + 4);
    atomicAdd(&g_cnt[c0.x], 1);
    atomicAdd(&g_cnt[c0.y], 1);
    atomicAdd(&g_cnt[c0.z], 1);
    atomicAdd(&g_cnt[c0.w], 1);
    atomicAdd(&g_cnt[c1.x], 1);
    atomicAdd(&g_cnt[c1.y], 1);
    atomicAdd(&g_cnt[c1.z], 1);
    atomicAdd(&g_cnt[c1.w], 1);
}

// ---------------- K2: FUSED scan (single kernel, device barrier) -------------
__global__ __launch_bounds__(SC_THREADS) void k_scanf() {
    __shared__ int sm[SC_THREADS];
    __shared__ int bp[SC_BLOCKS];
    int t = threadIdx.x, b = blockIdx.x;
    int base = (b * SC_THREADS + t) * SC_PER;
    int cnts[SC_PER];
    int s = 0;
    #pragma unroll
    for (int q = 0; q < SC_PER; ++q) {
        int i = base + q;
        cnts[q] = (i < N_NODES) ? g_cnt[i] : 0;
        s += cnts[q];
    }
    sm[t] = s;
    __syncthreads();
    for (int off = 1; off < SC_THREADS; off <<= 1) {
        int v = (t >= off) ? sm[t - off] : 0;
        __syncthreads();
        sm[t] += v;
        __syncthreads();
    }
    int tpref = sm[t] - s;
    if (t == SC_THREADS - 1) {
        g_bpart[b] = sm[t];
        __threadfence();
        atomicAdd(&g_arrive, 1);
    }
    if (t == 0) {
        while (atomicAdd(&g_arrive, 0) < SC_BLOCKS) { }
    }
    __syncthreads();
    if (t < SC_BLOCKS) bp[t] = g_bpart[t];
    __syncthreads();
    if (t == 0) {
        int run = 0;
        #pragma unroll 4
        for (int i = 0; i < SC_BLOCKS; ++i) { int c = bp[i]; bp[i] = run; run += c; }
    }
    __syncthreads();
    int run = bp[b] + tpref;
    #pragma unroll
    for (int q = 0; q < SC_PER; ++q) {
        int i = base + q;
        if (i < N_NODES) {
            int c = cnts[q];
            g_off[i] = run;
            g_cursor[i] = run;
            g_dinv[i] = rsqrtf((float)(c + 1));
            run += c;
            if (i == N_NODES - 1) g_off[N_NODES] = run;
        }
    }
}

// ---------------- K3: fill CSR source indices (standalone) ------------------
__global__ void k_fill(const int* __restrict__ ei) {
    int t = blockIdx.x * blockDim.x + threadIdx.x;
    int e8 = t * 8;
    if (e8 >= N_EDGES) return;
    int4 r0 = *(const int4*)(ei + e8);
    int4 r1 = *(const int4*)(ei + e8 + 4);
    int4 c0 = *(const int4*)(ei + N_EDGES + e8);
    int4 c1 = *(const int4*)(ei + N_EDGES + e8 + 4);
    int p0 = atomicAdd(&g_cursor[c0.x], 1);
    int p1 = atomicAdd(&g_cursor[c0.y], 1);
    int p2 = atomicAdd(&g_cursor[c0.z], 1);
    int p3 = atomicAdd(&g_cursor[c0.w], 1);
    int p4 = atomicAdd(&g_cursor[c1.x], 1);
    int p5 = atomicAdd(&g_cursor[c1.y], 1);
    int p6 = atomicAdd(&g_cursor[c1.z], 1);
    int p7 = atomicAdd(&g_cursor[c1.w], 1);
    g_csr_row[p0] = r0.x;
    g_csr_row[p1] = r0.y;
    g_csr_row[p2] = r0.z;
    g_csr_row[p3] = r0.w;
    g_csr_row[p4] = r1.x;
    g_csr_row[p5] = r1.y;
    g_csr_row[p6] = r1.z;
    g_csr_row[p7] = r1.w;
}

// ---------------- K5: layer-1 aggregation (dinv at gather) + BN stats -------
__global__ __launch_bounds__(256) void k_agg1(const float* __restrict__ b1) {
    __shared__ float s_sum[HID];
    __shared__ float s_sq[HID];
    const int tid  = threadIdx.x;
    const int lane = tid & 31;
    const int warp = tid >> 5;
    if (tid < HID) { s_sum[tid] = 0.f; s_sq[tid] = 0.f; }
    __syncthreads();

    int n = blockIdx.x * 8 + warp;
    if (n < N_NODES) {
        int s = g_off[n], e = g_off[n + 1];
        float dn = g_dinv[n];
        float4 v;
        {
            uint2 u = ((const uint2*)(g_h1s + (size_t)n * HID))[lane];
            float2 fa = __half22float2(*(__half2*)&u.x);
            float2 fb = __half22float2(*(__half2*)&u.y);
            v = make_float4(dn * fa.x, dn * fa.y, dn * fb.x, dn * fb.y);
        }
        int i = s;
        for (; i + 4 <= e; i += 4) {
            int r0 = g_csr_row[i];
            int r1 = g_csr_row[i + 1];
            int r2 = g_csr_row[i + 2];
            int r3 = g_csr_row[i + 3];
            float d0 = g_dinv[r0], d1 = g_dinv[r1], d2 = g_dinv[r2], d3 = g_dinv[r3];
            uint2 u0 = ((const uint2*)(g_h1s + (size_t)r0 * HID))[lane];
            uint2 u1 = ((const uint2*)(g_h1s + (size_t)r1 * HID))[lane];
            uint2 u2 = ((const uint2*)(g_h1s + (size_t)r2 * HID))[lane];
            uint2 u3 = ((const uint2*)(g_h1s + (size_t)r3 * HID))[lane];
            float2 a0 = __half22float2(*(__half2*)&u0.x), b0 = __half22float2(*(__half2*)&u0.y);
            float2 a1 = __half22float2(*(__half2*)&u1.x), b1f = __half22float2(*(__half2*)&u1.y);
            float2 a2 = __half22float2(*(__half2*)&u2.x), b2f = __half22float2(*(__half2*)&u2.y);
            float2 a3 = __half22float2(*(__half2*)&u3.x), b3f = __half22float2(*(__half2*)&u3.y);
            v.x = fmaf(d0, a0.x, v.x); v.y = fmaf(d0, a0.y, v.y);
            v.z = fmaf(d0, b0.x, v.z); v.w = fmaf(d0, b0.y, v.w);
            v.x = fmaf(d1, a1.x, v.x); v.y = fmaf(d1, a1.y, v.y);
            v.z = fmaf(d1, b1f.x, v.z); v.w = fmaf(d1, b1f.y, v.w);
            v.x = fmaf(d2, a2.x, v.x); v.y = fmaf(d2, a2.y, v.y);
            v.z = fmaf(d2, b2f.x, v.z); v.w = fmaf(d2, b2f.y, v.w);
            v.x = fmaf(d3, a3.x, v.x); v.y = fmaf(d3, a3.y, v.y);
            v.z = fmaf(d3, b3f.x, v.z); v.w = fmaf(d3, b3f.y, v.w);
        }
        for (; i < e; ++i) {
            int r0 = g_csr_row[i];
            float d0 = g_dinv[r0];
            uint2 u0 = ((const uint2*)(g_h1s + (size_t)r0 * HID))[lane];
            float2 a0 = __half22float2(*(__half2*)&u0.x), b0 = __half22float2(*(__half2*)&u0.y);
            v.x = fmaf(d0, a0.x, v.x); v.y = fmaf(d0, a0.y, v.y);
            v.z = fmaf(d0, b0.x, v.z); v.w = fmaf(d0, b0.y, v.w);
        }

        float vv[4] = {v.x, v.y, v.z, v.w};
        float hh[4];
        #pragma unroll
        for (int q = 0; q < 4; ++q) {
            int j = lane * 4 + q;
            hh[q] = fmaf(dn, vv[q], __ldg(b1 + j));
            atomicAdd(&s_sum[j], hh[q]);
            atomicAdd(&s_sq[j], hh[q] * hh[q]);
        }
        uint2 o;
        *(__half2*)&o.x = __floats2half2_rn(hh[0], hh[1]);
        *(__half2*)&o.y = __floats2half2_rn(hh[2], hh[3]);
        ((uint2*)(g_hpre + (size_t)n * HID))[lane] = o;
    }
    __syncthreads();
    if (tid < HID) {
        atomicAdd(&g_sums[tid], s_sum[tid]);
        atomicAdd(&g_sumsq[tid], s_sq[tid]);
    }
}

// ---------------- K8: BN (inline finalize) + relu + 128->2 GEMV -------------
__global__ __launch_bounds__(256) void k_node2(const float* __restrict__ W2,
                                               const float* __restrict__ gamma,
                                               const float* __restrict__ beta) {
    int n = (blockIdx.x * blockDim.x + threadIdx.x) >> 5;
    int lane = threadIdx.x & 31;
    if (n >= N_NODES) return;
    const float inv_n = 1.0f / (float)N_NODES;
    uint2 u = ((const uint2*)(g_hpre + (size_t)n * HID))[lane];
    float2 fa = __half22float2(*(__half2*)&u.x);
    float2 fb = __half22float2(*(__half2*)&u.y);
    float vv[4] = {fa.x, fa.y, fb.x, fb.y};
    float o0 = 0.f, o1 = 0.f;
    #pragma unroll
    for (int q = 0; q < 4; ++q) {
        int j = lane * 4 + q;
        float mu  = __ldg(g_sums + j) * inv_n;
        float var = __ldg(g_sumsq + j) * inv_n - mu * mu;
        float inv = rsqrtf(var + BN_EPS);
        float sc = __ldg(gamma + j) * inv;
        float sh = __ldg(beta + j) - mu * sc;
        float h = fmaf(vv[q], sc, sh);
        h = fmaxf(h, 0.f);
        o0 = fmaf(h, __ldg(W2 + j * 2 + 0), o0);
        o1 = fmaf(h, __ldg(W2 + j * 2 + 1), o1);
    }
    #pragma unroll
    for (int off = 16; off > 0; off >>= 1) {
        o0 += __shfl_xor_sync(0xffffffffu, o0, off);
        o1 += __shfl_xor_sync(0xffffffffu, o1, off);
    }
    if (lane == 0) {
        float d = g_dinv[n];
        g_h2s[n * 2 + 0] = o0 * d;
        g_h2s[n * 2 + 1] = o1 * d;
    }
}

// ---------------- K9: layer-2 aggregation (gather) + bias -------------------
__global__ __launch_bounds__(256) void k_out(const float* __restrict__ b2,
                                             float* __restrict__ out) {
    int n = (blockIdx.x * blockDim.x + threadIdx.x) >> 5;
    int lane = threadIdx.x & 31;
    if (n >= N_NODES) return;
    int s = g_off[n], e = g_off[n + 1];
    float o0 = 0.f, o1 = 0.f;
    for (int i = s + lane; i < e; i += 32) {
        int r = __ldg(g_csr_row + i);
        float2 v = *(const float2*)(g_h2s + (size_t)r * 2);
        o0 += v.x; o1 += v.y;
    }
    #pragma unroll
    for (int off = 16; off > 0; off >>= 1) {
        o0 += __shfl_xor_sync(0xffffffffu, o0, off);
        o1 += __shfl_xor_sync(0xffffffffu, o1, off);
    }
    if (lane == 0) {
        float d = g_dinv[n];
        float2 self = *(const float2*)(g_h2s + (size_t)n * 2);
        out[n * 2 + 0] = d * (o0 + self.x) + __ldg(b2 + 0);
        out[n * 2 + 1] = d * (o1 + self.y) + __ldg(b2 + 1);
    }
}

// ---------------- launch: two-stream fork-join (graph-capture branches) -----
extern "C" void kernel_launch(void* const* d_in, const int* in_sizes, int n_in,
                              void* d_out, int out_size) {
    const float* x  = (const float*)d_in[0];
    const int*   ei = (const int*)d_in[1];
    const float* fi = (const float*)d_in[2];
    const float* W1 = (const float*)d_in[3];
    const float* b1 = (const float*)d_in[4];
    const float* W2 = (const float*)d_in[5];
    const float* b2 = (const float*)d_in[6];
    const float* gm = (const float*)d_in[7];
    const float* bt = (const float*)d_in[8];
    float* out = (float*)d_out;

    cudaStream_t s2;
    cudaStreamCreateWithFlags(&s2, cudaStreamNonBlocking);
    cudaEvent_t ev_fork, ev_join;
    cudaEventCreateWithFlags(&ev_fork, cudaEventDisableTiming);
    cudaEventCreateWithFlags(&ev_join, cudaEventDisableTiming);

    k_prep<<<(N_NODES + 255) / 256, 256>>>(W1, fi);

    cudaEventRecord(ev_fork, cudaStreamPerThread);
    cudaStreamWaitEvent(s2, ev_fork, 0);

    // branch A (side stream): GEMM at 1 CTA/SM — leaves regs/smem for branch B
    k_gemm1<<<NBLK_GEMM, 256, 0, s2>>>(x);

    // branch B (main stream): CSR build chain at high occupancy
    k_deg<<<NBLK_EDGE, 256>>>(ei);
    k_scanf<<<SC_BLOCKS, SC_THREADS>>>();
    k_fill<<<NBLK_EDGE, 256>>>(ei);

    cudaEventRecord(ev_join, s2);
    cudaStreamWaitEvent(cudaStreamPerThread, ev_join, 0);

    k_agg1<<<(N_NODES + 7) / 8, 256>>>(b1);
    {
        long long tot = (long long)N_NODES * 32;
        k_node2<<<(unsigned)((tot + 255) / 256), 256>>>(W2, gm, bt);
        k_out<<<(unsigned)((tot + 255) / 256), 256>>>(b2, out);
    }
}

// round 14
// speedup vs baseline: 1.0468x; 1.0468x over previous
#include <cuda_runtime.h>
#include <cuda_fp16.h>
#include <cstdint>
#include <cstddef>

#define N_NODES 100000
#define N_EDGES 3200000
#define IN_DIM  256
#define HID     128
#define OUT_DIM 2
#define BN_EPS  1e-5f

#define SC_BLOCKS 100
#define SC_THREADS 256
#define SC_PER 4   // 100*256*4 = 102400 >= N_NODES

#define GBM 128
#define GBK 32
#define A_S 36
#define B_S 132
#define NBLK_GEMM ((N_NODES + GBM - 1) / GBM)          // 782
#define NBLK_EDGE ((N_EDGES / 8 + 255) / 256)          // 1563
#define AGG_NPW 4                                       // nodes per warp in agg1

// ---------------- scratch (static device globals; no runtime alloc) --------
__device__ __align__(16) float  g_dinv[N_NODES];
__device__ __align__(16) __half g_h1s[(size_t)N_NODES * HID];   // fp16 h1 (unscaled)
__device__ __align__(16) __half g_hpre[(size_t)N_NODES * HID];  // fp16 pre-BN h
__device__ __align__(16) float  g_h2s[N_NODES * OUT_DIM];
__device__ __align__(16) float  g_W1s[IN_DIM * HID];            // tf32-rounded W1*sig(fi)
__device__ __align__(16) float  g_sums[HID];
__device__ __align__(16) float  g_sumsq[HID];
// CSR by destination
__device__ __align__(16) int    g_cnt[N_NODES];
__device__ __align__(16) int    g_off[N_NODES + 1];
__device__ __align__(16) int    g_cursor[N_NODES];
__device__ __align__(16) int    g_csr_row[N_EDGES];
// fused-scan scratch
__device__ __align__(16) int    g_bpart[SC_BLOCKS];
__device__ int                  g_arrive;

// ---------------- helpers ---------------------------------------------------
__device__ __forceinline__ float to_tf32(float x) {
    uint32_t u;
    asm("cvt.rna.tf32.f32 %0, %1;" : "=r"(u) : "f"(x));
    return __uint_as_float(u);
}

__device__ __forceinline__ void mma_tf32(float* c,
                                         uint32_t a0, uint32_t a1, uint32_t a2, uint32_t a3,
                                         uint32_t b0, uint32_t b1) {
    asm volatile(
        "mma.sync.aligned.m16n8k8.row.col.f32.tf32.tf32.f32 "
        "{%0,%1,%2,%3}, {%4,%5,%6,%7}, {%8,%9}, {%0,%1,%2,%3};"
        : "+f"(c[0]), "+f"(c[1]), "+f"(c[2]), "+f"(c[3])
        : "r"(a0), "r"(a1), "r"(a2), "r"(a3), "r"(b0), "r"(b1));
}

// ---------------- K0: prep (fold sigmoid into W1 -> tf32, zero counters) ----
__global__ void k_prep(const float* __restrict__ W1, const float* __restrict__ fi) {
    int i = blockIdx.x * blockDim.x + threadIdx.x;
    if (i < IN_DIM * HID) {
        int k = i / HID;
        float s = 1.0f / (1.0f + __expf(-fi[k]));
        g_W1s[i] = to_tf32(W1[i] * s);
    }
    if (i < N_NODES) g_cnt[i] = 0;
    if (i < HID) { g_sums[i] = 0.0f; g_sumsq[i] = 0.0f; }
    if (i == 0) g_arrive = 0;
}

// ---------------- K_GEMM: tf32 GEMM, register A-prefetch, 2 CTA/SM ----------
__global__ __launch_bounds__(256, 2) void k_gemm1(const float* __restrict__ x) {
    __shared__ float As[GBM * A_S];
    __shared__ float Bs[GBK * B_S];
    const int m0   = blockIdx.x * GBM;
    const int tid  = threadIdx.x;
    const int lane = tid & 31;
    const int wid  = tid >> 5;
    const int wm   = wid >> 2;
    const int wn   = wid & 3;
    const int grp  = lane >> 2;
    const int tg   = lane & 3;

    float acc[4][4][4];
    #pragma unroll
    for (int im = 0; im < 4; ++im)
        #pragma unroll
        for (int in = 0; in < 4; ++in)
            #pragma unroll
            for (int q = 0; q < 4; ++q) acc[im][in][q] = 0.f;

    float4 ra[4];

    auto loadA = [&](int k0) {
        #pragma unroll
        for (int p = 0; p < 4; ++p) {
            int slot = tid + p * 256;
            int r = slot >> 3;
            int q = slot & 7;
            int gm = m0 + r;
            ra[p] = make_float4(0.f, 0.f, 0.f, 0.f);
            if (gm < N_NODES)
                ra[p] = *(const float4*)(x + (size_t)gm * IN_DIM + k0 + q * 4);
        }
    };
    auto storeA = [&]() {
        #pragma unroll
        for (int p = 0; p < 4; ++p) {
            int slot = tid + p * 256;
            int r = slot >> 3;
            int q = slot & 7;
            float* dst = As + r * A_S + q * 4;
            dst[0] = to_tf32(ra[p].x);
            dst[1] = to_tf32(ra[p].y);
            dst[2] = to_tf32(ra[p].z);
            dst[3] = to_tf32(ra[p].w);
        }
    };
    auto loadstoreB = [&](int k0) {
        #pragma unroll
        for (int p = 0; p < 4; ++p) {
            int slot = tid + p * 256;
            int r = slot >> 5;
            int c = slot & 31;
            float4 v = *(const float4*)(g_W1s + (size_t)(k0 + r) * HID + c * 4);
            *(float4*)(Bs + r * B_S + c * 4) = v;   // already tf32-rounded
        }
    };

    const int NT = IN_DIM / GBK;   // 8
    loadA(0);
    for (int t = 0; t < NT; ++t) {
        storeA();
        loadstoreB(t * GBK);
        __syncthreads();
        if (t + 1 < NT) loadA((t + 1) * GBK);

        #pragma unroll
        for (int ks = 0; ks < GBK; ks += 8) {
            uint32_t a[4][4], b[4][2];
            #pragma unroll
            for (int im = 0; im < 4; ++im) {
                int mb = wm * 64 + im * 16;
                const float* pa = As + (mb + grp) * A_S + ks + tg;
                a[im][0] = __float_as_uint(pa[0]);
                a[im][1] = __float_as_uint(pa[8 * A_S]);
                a[im][2] = __float_as_uint(pa[4]);
                a[im][3] = __float_as_uint(pa[8 * A_S + 4]);
            }
            #pragma unroll
            for (int in = 0; in < 4; ++in) {
                int nb = wn * 32 + in * 8 + grp;
                const float* pb = Bs + (ks + tg) * B_S + nb;
                b[in][0] = __float_as_uint(pb[0]);
                b[in][1] = __float_as_uint(pb[4 * B_S]);
            }
            #pragma unroll
            for (int im = 0; im < 4; ++im)
                #pragma unroll
                for (int in = 0; in < 4; ++in)
                    mma_tf32(acc[im][in], a[im][0], a[im][1], a[im][2], a[im][3],
                             b[in][0], b[in][1]);
        }
        __syncthreads();
    }

    #pragma unroll
    for (int im = 0; im < 4; ++im) {
        int r0 = m0 + wm * 64 + im * 16 + grp;
        int r1 = r0 + 8;
        #pragma unroll
        for (int in = 0; in < 4; ++in) {
            int col = wn * 32 + in * 8 + tg * 2;
            if (r0 < N_NODES) {
                __half2 h = __floats2half2_rn(acc[im][in][0], acc[im][in][1]);
                *(__half2*)(g_h1s + (size_t)r0 * HID + col) = h;
            }
            if (r1 < N_NODES) {
                __half2 h = __floats2half2_rn(acc[im][in][2], acc[im][in][3]);
                *(__half2*)(g_h1s + (size_t)r1 * HID + col) = h;
            }
        }
    }
}

// ---------------- K1: in-degree histogram ------------------------------------
__global__ void k_deg(const int* __restrict__ ei) {
    int t = blockIdx.x * blockDim.x + threadIdx.x;
    int e8 = t * 8;
    if (e8 >= N_EDGES) return;
    int4 c0 = *(const int4*)(ei + N_EDGES + e8);
    int4 c1 = *(const int4*)(ei + N_EDGES + e8 + 4);
    atomicAdd(&g_cnt[c0.x], 1);
    atomicAdd(&g_cnt[c0.y], 1);
    atomicAdd(&g_cnt[c0.z], 1);
    atomicAdd(&g_cnt[c0.w], 1);
    atomicAdd(&g_cnt[c1.x], 1);
    atomicAdd(&g_cnt[c1.y], 1);
    atomicAdd(&g_cnt[c1.z], 1);
    atomicAdd(&g_cnt[c1.w], 1);
}

// ---------------- K2: FUSED scan (single kernel, device barrier) -------------
__global__ __launch_bounds__(SC_THREADS) void k_scanf() {
    __shared__ int sm[SC_THREADS];
    __shared__ int bp[SC_BLOCKS];
    int t = threadIdx.x, b = blockIdx.x;
    int base = (b * SC_THREADS + t) * SC_PER;
    int cnts[SC_PER];
    int s = 0;
    #pragma unroll
    for (int q = 0; q < SC_PER; ++q) {
        int i = base + q;
        cnts[q] = (i < N_NODES) ? g_cnt[i] : 0;
        s += cnts[q];
    }
    sm[t] = s;
    __syncthreads();
    for (int off = 1; off < SC_THREADS; off <<= 1) {
        int v = (t >= off) ? sm[t - off] : 0;
        __syncthreads();
        sm[t] += v;
        __syncthreads();
    }
    int tpref = sm[t] - s;
    if (t == SC_THREADS - 1) {
        g_bpart[b] = sm[t];
        __threadfence();
        atomicAdd(&g_arrive, 1);
    }
    if (t == 0) {
        while (atomicAdd(&g_arrive, 0) < SC_BLOCKS) { }
    }
    __syncthreads();
    if (t < SC_BLOCKS) bp[t] = g_bpart[t];
    __syncthreads();
    if (t == 0) {
        int run = 0;
        #pragma unroll 4
        for (int i = 0; i < SC_BLOCKS; ++i) { int c = bp[i]; bp[i] = run; run += c; }
    }
    __syncthreads();
    int run = bp[b] + tpref;
    #pragma unroll
    for (int q = 0; q < SC_PER; ++q) {
        int i = base + q;
        if (i < N_NODES) {
            int c = cnts[q];
            g_off[i] = run;
            g_cursor[i] = run;
            g_dinv[i] = rsqrtf((float)(c + 1));
            run += c;
            if (i == N_NODES - 1) g_off[N_NODES] = run;
        }
    }
}

// ---------------- K3: fill CSR source indices --------------------------------
__global__ void k_fill(const int* __restrict__ ei) {
    int t = blockIdx.x * blockDim.x + threadIdx.x;
    int e8 = t * 8;
    if (e8 >= N_EDGES) return;
    int4 r0 = *(const int4*)(ei + e8);
    int4 r1 = *(const int4*)(ei + e8 + 4);
    int4 c0 = *(const int4*)(ei + N_EDGES + e8);
    int4 c1 = *(const int4*)(ei + N_EDGES + e8 + 4);
    int p0 = atomicAdd(&g_cursor[c0.x], 1);
    int p1 = atomicAdd(&g_cursor[c0.y], 1);
    int p2 = atomicAdd(&g_cursor[c0.z], 1);
    int p3 = atomicAdd(&g_cursor[c0.w], 1);
    int p4 = atomicAdd(&g_cursor[c1.x], 1);
    int p5 = atomicAdd(&g_cursor[c1.y], 1);
    int p6 = atomicAdd(&g_cursor[c1.z], 1);
    int p7 = atomicAdd(&g_cursor[c1.w], 1);
    g_csr_row[p0] = r0.x;
    g_csr_row[p1] = r0.y;
    g_csr_row[p2] = r0.z;
    g_csr_row[p3] = r0.w;
    g_csr_row[p4] = r1.x;
    g_csr_row[p5] = r1.y;
    g_csr_row[p6] = r1.z;
    g_csr_row[p7] = r1.w;
}

// ---------------- K5: agg1 — 4 contiguous nodes per warp, reg-local stats ---
__global__ __launch_bounds__(256) void k_agg1(const float* __restrict__ b1) {
    __shared__ float s_sum[HID];
    __shared__ float s_sq[HID];
    const int tid  = threadIdx.x;
    const int lane = tid & 31;
    const int warp = tid >> 5;
    if (tid < HID) { s_sum[tid] = 0.f; s_sq[tid] = 0.f; }
    __syncthreads();

    float sreg[4]  = {0.f, 0.f, 0.f, 0.f};
    float sqreg[4] = {0.f, 0.f, 0.f, 0.f};
    const float bb[4] = {__ldg(b1 + lane * 4 + 0), __ldg(b1 + lane * 4 + 1),
                         __ldg(b1 + lane * 4 + 2), __ldg(b1 + lane * 4 + 3)};

    int n0 = (blockIdx.x * 8 + warp) * AGG_NPW;
    #pragma unroll
    for (int k = 0; k < AGG_NPW; ++k) {
        int n = n0 + k;
        if (n >= N_NODES) break;
        int s = g_off[n], e = g_off[n + 1];
        float dn = g_dinv[n];
        float4 v;
        {
            uint2 u = ((const uint2*)(g_h1s + (size_t)n * HID))[lane];
            float2 fa = __half22float2(*(__half2*)&u.x);
            float2 fb = __half22float2(*(__half2*)&u.y);
            v = make_float4(dn * fa.x, dn * fa.y, dn * fb.x, dn * fb.y);
        }
        int i = s;
        for (; i + 4 <= e; i += 4) {
            int r0 = g_csr_row[i];
            int r1 = g_csr_row[i + 1];
            int r2 = g_csr_row[i + 2];
            int r3 = g_csr_row[i + 3];
            float d0 = g_dinv[r0], d1 = g_dinv[r1], d2 = g_dinv[r2], d3 = g_dinv[r3];
            uint2 u0 = ((const uint2*)(g_h1s + (size_t)r0 * HID))[lane];
            uint2 u1 = ((const uint2*)(g_h1s + (size_t)r1 * HID))[lane];
            uint2 u2 = ((const uint2*)(g_h1s + (size_t)r2 * HID))[lane];
            uint2 u3 = ((const uint2*)(g_h1s + (size_t)r3 * HID))[lane];
            float2 a0 = __half22float2(*(__half2*)&u0.x), b0 = __half22float2(*(__half2*)&u0.y);
            float2 a1 = __half22float2(*(__half2*)&u1.x), b1f = __half22float2(*(__half2*)&u1.y);
            float2 a2 = __half22float2(*(__half2*)&u2.x), b2f = __half22float2(*(__half2*)&u2.y);
            float2 a3 = __half22float2(*(__half2*)&u3.x), b3f = __half22float2(*(__half2*)&u3.y);
            v.x = fmaf(d0, a0.x, v.x); v.y = fmaf(d0, a0.y, v.y);
            v.z = fmaf(d0, b0.x, v.z); v.w = fmaf(d0, b0.y, v.w);
            v.x = fmaf(d1, a1.x, v.x); v.y = fmaf(d1, a1.y, v.y);
            v.z = fmaf(d1, b1f.x, v.z); v.w = fmaf(d1, b1f.y, v.w);
            v.x = fmaf(d2, a2.x, v.x); v.y = fmaf(d2, a2.y, v.y);
            v.z = fmaf(d2, b2f.x, v.z); v.w = fmaf(d2, b2f.y, v.w);
            v.x = fmaf(d3, a3.x, v.x); v.y = fmaf(d3, a3.y, v.y);
            v.z = fmaf(d3, b3f.x, v.z); v.w = fmaf(d3, b3f.y, v.w);
        }
        for (; i < e; ++i) {
            int r0 = g_csr_row[i];
            float d0 = g_dinv[r0];
            uint2 u0 = ((const uint2*)(g_h1s + (size_t)r0 * HID))[lane];
            float2 a0 = __half22float2(*(__half2*)&u0.x), b0 = __half22float2(*(__half2*)&u0.y);
            v.x = fmaf(d0, a0.x, v.x); v.y = fmaf(d0, a0.y, v.y);
            v.z = fmaf(d0, b0.x, v.z); v.w = fmaf(d0, b0.y, v.w);
        }

        float vv[4] = {v.x, v.y, v.z, v.w};
        float hh[4];
        #pragma unroll
        for (int q = 0; q < 4; ++q) {
            hh[q] = fmaf(dn, vv[q], bb[q]);
            sreg[q]  += hh[q];
            sqreg[q] += hh[q] * hh[q];
        }
        uint2 o;
        *(__half2*)&o.x = __floats2half2_rn(hh[0], hh[1]);
        *(__half2*)&o.y = __floats2half2_rn(hh[2], hh[3]);
        ((uint2*)(g_hpre + (size_t)n * HID))[lane] = o;
    }

    // one smem-atomic set per warp (8 warps/block), then one global set
    #pragma unroll
    for (int q = 0; q < 4; ++q) {
        atomicAdd(&s_sum[lane * 4 + q], sreg[q]);
        atomicAdd(&s_sq[lane * 4 + q], sqreg[q]);
    }
    __syncthreads();
    if (tid < HID) {
        atomicAdd(&g_sums[tid], s_sum[tid]);
        atomicAdd(&g_sumsq[tid], s_sq[tid]);
    }
}

// ---------------- K8: BN (inline finalize) + relu + 128->2 GEMV -------------
__global__ __launch_bounds__(256) void k_node2(const float* __restrict__ W2,
                                               const float* __restrict__ gamma,
                                               const float* __restrict__ beta) {
    int n = (blockIdx.x * blockDim.x + threadIdx.x) >> 5;
    int lane = threadIdx.x & 31;
    if (n >= N_NODES) return;
    const float inv_n = 1.0f / (float)N_NODES;
    uint2 u = ((const uint2*)(g_hpre + (size_t)n * HID))[lane];
    float2 fa = __half22float2(*(__half2*)&u.x);
    float2 fb = __half22float2(*(__half2*)&u.y);
    float vv[4] = {fa.x, fa.y, fb.x, fb.y};
    float o0 = 0.f, o1 = 0.f;
    #pragma unroll
    for (int q = 0; q < 4; ++q) {
        int j = lane * 4 + q;
        float mu  = __ldg(g_sums + j) * inv_n;
        float var = __ldg(g_sumsq + j) * inv_n - mu * mu;
        float inv = rsqrtf(var + BN_EPS);
        float sc = __ldg(gamma + j) * inv;
        float sh = __ldg(beta + j) - mu * sc;
        float h = fmaf(vv[q], sc, sh);
        h = fmaxf(h, 0.f);
        o0 = fmaf(h, __ldg(W2 + j * 2 + 0), o0);
        o1 = fmaf(h, __ldg(W2 + j * 2 + 1), o1);
    }
    #pragma unroll
    for (int off = 16; off > 0; off >>= 1) {
        o0 += __shfl_xor_sync(0xffffffffu, o0, off);
        o1 += __shfl_xor_sync(0xffffffffu, o1, off);
    }
    if (lane == 0) {
        float d = g_dinv[n];
        g_h2s[n * 2 + 0] = o0 * d;
        g_h2s[n * 2 + 1] = o1 * d;
    }
}

// ---------------- K9: layer-2 aggregation (gather) + bias -------------------
__global__ __launch_bounds__(256) void k_out(const float* __restrict__ b2,
                                             float* __restrict__ out) {
    int n = (blockIdx.x * blockDim.x + threadIdx.x) >> 5;
    int lane = threadIdx.x & 31;
    if (n >= N_NODES) return;
    int s = g_off[n], e = g_off[n + 1];
    float o0 = 0.f, o1 = 0.f;
    for (int i = s + lane; i < e; i += 32) {
        int r = __ldg(g_csr_row + i);
        float2 v = *(const float2*)(g_h2s + (size_t)r * 2);
        o0 += v.x; o1 += v.y;
    }
    #pragma unroll
    for (int off = 16; off > 0; off >>= 1) {
        o0 += __shfl_xor_sync(0xffffffffu, o0, off);
        o1 += __shfl_xor_sync(0xffffffffu, o1, off);
    }
    if (lane == 0) {
        float d = g_dinv[n];
        float2 self = *(const float2*)(g_h2s + (size_t)n * 2);
        out[n * 2 + 0] = d * (o0 + self.x) + __ldg(b2 + 0);
        out[n * 2 + 1] = d * (o1 + self.y) + __ldg(b2 + 1);
    }
}

// ---------------- launch (simple sequence; overlap attempts retired) --------
extern "C" void kernel_launch(void* const* d_in, const int* in_sizes, int n_in,
                              void* d_out, int out_size) {
    const float* x  = (const float*)d_in[0];
    const int*   ei = (const int*)d_in[1];
    const float* fi = (const float*)d_in[2];
    const float* W1 = (const float*)d_in[3];
    const float* b1 = (const float*)d_in[4];
    const float* W2 = (const float*)d_in[5];
    const float* b2 = (const float*)d_in[6];
    const float* gm = (const float*)d_in[7];
    const float* bt = (const float*)d_in[8];
    float* out = (float*)d_out;

    k_prep<<<(N_NODES + 255) / 256, 256>>>(W1, fi);                        // 0
    k_gemm1<<<NBLK_GEMM, 256>>>(x);                                        // 1
    k_deg<<<NBLK_EDGE, 256>>>(ei);                                         // 2
    k_scanf<<<SC_BLOCKS, SC_THREADS>>>();                                  // 3 (ncu slot)
    k_fill<<<NBLK_EDGE, 256>>>(ei);                                        // 4
    k_agg1<<<(N_NODES + 8 * AGG_NPW - 1) / (8 * AGG_NPW), 256>>>(b1);      // 5
    {
        long long tot = (long long)N_NODES * 32;
        k_node2<<<(unsigned)((tot + 255) / 256), 256>>>(W2, gm, bt);       // 6
        k_out<<<(unsigned)((tot + 255) / 256), 256>>>(b2, out);            // 7
    }
}

// round 15
// speedup vs baseline: 1.1219x; 1.0717x over previous
#include <cuda_runtime.h>
#include <cuda_fp16.h>
#include <cstdint>
#include <cstddef>

#define N_NODES 100000
#define N_EDGES 3200000
#define IN_DIM  256
#define HID     128
#define OUT_DIM 2
#define BN_EPS  1e-5f

#define SC_BLOCKS 100
#define SC_THREADS 256
#define SC_PER 4   // 100*256*4 = 102400 >= N_NODES

#define GBM 128
#define GBK 32
#define A_S 36
#define B_S 132
#define NBLK_GEMM ((N_NODES + GBM - 1) / GBM)          // 782
#define NBLK_EDGE ((N_EDGES / 8 + 255) / 256)          // 1563
#define AGG_NPW 4                                       // nodes per warp in agg1

// ---------------- scratch (static device globals; no runtime alloc) --------
__device__ __align__(16) float  g_dinv[N_NODES];
__device__ __align__(16) __half g_h1s[(size_t)N_NODES * HID];   // fp16 dinv[r]*h1
__device__ __align__(16) __half g_hpre[(size_t)N_NODES * HID];  // fp16 pre-BN h
__device__ __align__(16) float  g_h2s[N_NODES * OUT_DIM];
__device__ __align__(16) float  g_W1s[IN_DIM * HID];            // tf32-rounded W1*sig(fi)
__device__ __align__(16) float  g_sums[HID];
__device__ __align__(16) float  g_sumsq[HID];
// CSR by destination
__device__ __align__(16) int    g_cnt[N_NODES];
__device__ __align__(16) int    g_off[N_NODES + 1];
__device__ __align__(16) int    g_cursor[N_NODES];
__device__ __align__(16) int    g_csr_row[N_EDGES];
// fused-scan scratch
__device__ __align__(16) int    g_bpart[SC_BLOCKS];
__device__ int                  g_arrive;

// ---------------- helpers ---------------------------------------------------
__device__ __forceinline__ float to_tf32(float x) {
    uint32_t u;
    asm("cvt.rna.tf32.f32 %0, %1;" : "=r"(u) : "f"(x));
    return __uint_as_float(u);
}

__device__ __forceinline__ void mma_tf32(float* c,
                                         uint32_t a0, uint32_t a1, uint32_t a2, uint32_t a3,
                                         uint32_t b0, uint32_t b1) {
    asm volatile(
        "mma.sync.aligned.m16n8k8.row.col.f32.tf32.tf32.f32 "
        "{%0,%1,%2,%3}, {%4,%5,%6,%7}, {%8,%9}, {%0,%1,%2,%3};"
        : "+f"(c[0]), "+f"(c[1]), "+f"(c[2]), "+f"(c[3])
        : "r"(a0), "r"(a1), "r"(a2), "r"(a3), "r"(b0), "r"(b1));
}

// ---------------- K0: prep (fold sigmoid into W1 -> tf32, zero counters) ----
__global__ void k_prep(const float* __restrict__ W1, const float* __restrict__ fi) {
    int i = blockIdx.x * blockDim.x + threadIdx.x;
    if (i < IN_DIM * HID) {
        int k = i / HID;
        float s = 1.0f / (1.0f + __expf(-fi[k]));
        g_W1s[i] = to_tf32(W1[i] * s);
    }
    if (i < N_NODES) g_cnt[i] = 0;
    if (i < HID) { g_sums[i] = 0.0f; g_sumsq[i] = 0.0f; }
    if (i == 0) g_arrive = 0;
}

// ---------------- K1: in-degree histogram ------------------------------------
__global__ void k_deg(const int* __restrict__ ei) {
    int t = blockIdx.x * blockDim.x + threadIdx.x;
    int e8 = t * 8;
    if (e8 >= N_EDGES) return;
    int4 c0 = *(const int4*)(ei + N_EDGES + e8);
    int4 c1 = *(const int4*)(ei + N_EDGES + e8 + 4);
    atomicAdd(&g_cnt[c0.x], 1);
    atomicAdd(&g_cnt[c0.y], 1);
    atomicAdd(&g_cnt[c0.z], 1);
    atomicAdd(&g_cnt[c0.w], 1);
    atomicAdd(&g_cnt[c1.x], 1);
    atomicAdd(&g_cnt[c1.y], 1);
    atomicAdd(&g_cnt[c1.z], 1);
    atomicAdd(&g_cnt[c1.w], 1);
}

// ---------------- K2: FUSED scan (single kernel, device barrier) -------------
__global__ __launch_bounds__(SC_THREADS) void k_scanf() {
    __shared__ int sm[SC_THREADS];
    __shared__ int bp[SC_BLOCKS];
    int t = threadIdx.x, b = blockIdx.x;
    int base = (b * SC_THREADS + t) * SC_PER;
    int cnts[SC_PER];
    int s = 0;
    #pragma unroll
    for (int q = 0; q < SC_PER; ++q) {
        int i = base + q;
        cnts[q] = (i < N_NODES) ? g_cnt[i] : 0;
        s += cnts[q];
    }
    sm[t] = s;
    __syncthreads();
    for (int off = 1; off < SC_THREADS; off <<= 1) {
        int v = (t >= off) ? sm[t - off] : 0;
        __syncthreads();
        sm[t] += v;
        __syncthreads();
    }
    int tpref = sm[t] - s;
    if (t == SC_THREADS - 1) {
        g_bpart[b] = sm[t];
        __threadfence();
        atomicAdd(&g_arrive, 1);
    }
    if (t == 0) {
        while (atomicAdd(&g_arrive, 0) < SC_BLOCKS) { }
    }
    __syncthreads();
    if (t < SC_BLOCKS) bp[t] = g_bpart[t];
    __syncthreads();
    if (t == 0) {
        int run = 0;
        #pragma unroll 4
        for (int i = 0; i < SC_BLOCKS; ++i) { int c = bp[i]; bp[i] = run; run += c; }
    }
    __syncthreads();
    int run = bp[b] + tpref;
    #pragma unroll
    for (int q = 0; q < SC_PER; ++q) {
        int i = base + q;
        if (i < N_NODES) {
            int c = cnts[q];
            g_off[i] = run;
            g_cursor[i] = run;
            g_dinv[i] = rsqrtf((float)(c + 1));
            run += c;
            if (i == N_NODES - 1) g_off[N_NODES] = run;
        }
    }
}

// ---------------- K3: fill CSR source indices --------------------------------
__global__ void k_fill(const int* __restrict__ ei) {
    int t = blockIdx.x * blockDim.x + threadIdx.x;
    int e8 = t * 8;
    if (e8 >= N_EDGES) return;
    int4 r0 = *(const int4*)(ei + e8);
    int4 r1 = *(const int4*)(ei + e8 + 4);
    int4 c0 = *(const int4*)(ei + N_EDGES + e8);
    int4 c1 = *(const int4*)(ei + N_EDGES + e8 + 4);
    int p0 = atomicAdd(&g_cursor[c0.x], 1);
    int p1 = atomicAdd(&g_cursor[c0.y], 1);
    int p2 = atomicAdd(&g_cursor[c0.z], 1);
    int p3 = atomicAdd(&g_cursor[c0.w], 1);
    int p4 = atomicAdd(&g_cursor[c1.x], 1);
    int p5 = atomicAdd(&g_cursor[c1.y], 1);
    int p6 = atomicAdd(&g_cursor[c1.z], 1);
    int p7 = atomicAdd(&g_cursor[c1.w], 1);
    g_csr_row[p0] = r0.x;
    g_csr_row[p1] = r0.y;
    g_csr_row[p2] = r0.z;
    g_csr_row[p3] = r0.w;
    g_csr_row[p4] = r1.x;
    g_csr_row[p5] = r1.y;
    g_csr_row[p6] = r1.z;
    g_csr_row[p7] = r1.w;
}

// ---------------- K4: tf32 GEMM, reg A-prefetch, dinv-scaled fp16 epilogue --
// Runs AFTER k_scanf (dinv ready): h1s = dinv[row] * (x @ W1s), fp16.
__global__ __launch_bounds__(256, 2) void k_gemm1(const float* __restrict__ x) {
    __shared__ float As[GBM * A_S];
    __shared__ float Bs[GBK * B_S];
    const int m0   = blockIdx.x * GBM;
    const int tid  = threadIdx.x;
    const int lane = tid & 31;
    const int wid  = tid >> 5;
    const int wm   = wid >> 2;
    const int wn   = wid & 3;
    const int grp  = lane >> 2;
    const int tg   = lane & 3;

    float acc[4][4][4];
    #pragma unroll
    for (int im = 0; im < 4; ++im)
        #pragma unroll
        for (int in = 0; in < 4; ++in)
            #pragma unroll
            for (int q = 0; q < 4; ++q) acc[im][in][q] = 0.f;

    float4 ra[4];

    auto loadA = [&](int k0) {
        #pragma unroll
        for (int p = 0; p < 4; ++p) {
            int slot = tid + p * 256;
            int r = slot >> 3;
            int q = slot & 7;
            int gm = m0 + r;
            ra[p] = make_float4(0.f, 0.f, 0.f, 0.f);
            if (gm < N_NODES)
                ra[p] = *(const float4*)(x + (size_t)gm * IN_DIM + k0 + q * 4);
        }
    };
    auto storeA = [&]() {
        #pragma unroll
        for (int p = 0; p < 4; ++p) {
            int slot = tid + p * 256;
            int r = slot >> 3;
            int q = slot & 7;
            float* dst = As + r * A_S + q * 4;
            dst[0] = to_tf32(ra[p].x);
            dst[1] = to_tf32(ra[p].y);
            dst[2] = to_tf32(ra[p].z);
            dst[3] = to_tf32(ra[p].w);
        }
    };
    auto loadstoreB = [&](int k0) {
        #pragma unroll
        for (int p = 0; p < 4; ++p) {
            int slot = tid + p * 256;
            int r = slot >> 5;
            int c = slot & 31;
            float4 v = *(const float4*)(g_W1s + (size_t)(k0 + r) * HID + c * 4);
            *(float4*)(Bs + r * B_S + c * 4) = v;   // already tf32-rounded
        }
    };

    const int NT = IN_DIM / GBK;   // 8
    loadA(0);
    for (int t = 0; t < NT; ++t) {
        storeA();
        loadstoreB(t * GBK);
        __syncthreads();
        if (t + 1 < NT) loadA((t + 1) * GBK);

        #pragma unroll
        for (int ks = 0; ks < GBK; ks += 8) {
            uint32_t a[4][4], b[4][2];
            #pragma unroll
            for (int im = 0; im < 4; ++im) {
                int mb = wm * 64 + im * 16;
                const float* pa = As + (mb + grp) * A_S + ks + tg;
                a[im][0] = __float_as_uint(pa[0]);
                a[im][1] = __float_as_uint(pa[8 * A_S]);
                a[im][2] = __float_as_uint(pa[4]);
                a[im][3] = __float_as_uint(pa[8 * A_S + 4]);
            }
            #pragma unroll
            for (int in = 0; in < 4; ++in) {
                int nb = wn * 32 + in * 8 + grp;
                const float* pb = Bs + (ks + tg) * B_S + nb;
                b[in][0] = __float_as_uint(pb[0]);
                b[in][1] = __float_as_uint(pb[4 * B_S]);
            }
            #pragma unroll
            for (int im = 0; im < 4; ++im)
                #pragma unroll
                for (int in = 0; in < 4; ++in)
                    mma_tf32(acc[im][in], a[im][0], a[im][1], a[im][2], a[im][3],
                             b[in][0], b[in][1]);
        }
        __syncthreads();
    }

    #pragma unroll
    for (int im = 0; im < 4; ++im) {
        int r0 = m0 + wm * 64 + im * 16 + grp;
        int r1 = r0 + 8;
        float d0 = (r0 < N_NODES) ? g_dinv[r0] : 0.f;
        float d1 = (r1 < N_NODES) ? g_dinv[r1] : 0.f;
        #pragma unroll
        for (int in = 0; in < 4; ++in) {
            int col = wn * 32 + in * 8 + tg * 2;
            if (r0 < N_NODES) {
                __half2 h = __floats2half2_rn(acc[im][in][0] * d0, acc[im][in][1] * d0);
                *(__half2*)(g_h1s + (size_t)r0 * HID + col) = h;
            }
            if (r1 < N_NODES) {
                __half2 h = __floats2half2_rn(acc[im][in][2] * d1, acc[im][in][3] * d1);
                *(__half2*)(g_h1s + (size_t)r1 * HID + col) = h;
            }
        }
    }
}

// ---------------- K5: agg1 — pre-scaled h1 gathers, streaming hints ---------
__global__ __launch_bounds__(256) void k_agg1(const float* __restrict__ b1) {
    __shared__ float s_sum[HID];
    __shared__ float s_sq[HID];
    const int tid  = threadIdx.x;
    const int lane = tid & 31;
    const int warp = tid >> 5;
    if (tid < HID) { s_sum[tid] = 0.f; s_sq[tid] = 0.f; }
    __syncthreads();

    float sreg[4]  = {0.f, 0.f, 0.f, 0.f};
    float sqreg[4] = {0.f, 0.f, 0.f, 0.f};
    const float bb[4] = {__ldg(b1 + lane * 4 + 0), __ldg(b1 + lane * 4 + 1),
                         __ldg(b1 + lane * 4 + 2), __ldg(b1 + lane * 4 + 3)};

    int n0 = (blockIdx.x * 8 + warp) * AGG_NPW;
    #pragma unroll
    for (int k = 0; k < AGG_NPW; ++k) {
        int n = n0 + k;
        if (n >= N_NODES) break;
        int s = g_off[n], e = g_off[n + 1];
        float dn = g_dinv[n];
        float4 v;
        {   // self loop: h1s already dinv[n]-scaled
            uint2 u = ((const uint2*)(g_h1s + (size_t)n * HID))[lane];
            float2 fa = __half22float2(*(__half2*)&u.x);
            float2 fb = __half22float2(*(__half2*)&u.y);
            v = make_float4(fa.x, fa.y, fb.x, fb.y);
        }
        int i = s;
        for (; i + 4 <= e; i += 4) {
            int r0 = __ldcs(g_csr_row + i);
            int r1 = __ldcs(g_csr_row + i + 1);
            int r2 = __ldcs(g_csr_row + i + 2);
            int r3 = __ldcs(g_csr_row + i + 3);
            uint2 u0 = ((const uint2*)(g_h1s + (size_t)r0 * HID))[lane];
            uint2 u1 = ((const uint2*)(g_h1s + (size_t)r1 * HID))[lane];
            uint2 u2 = ((const uint2*)(g_h1s + (size_t)r2 * HID))[lane];
            uint2 u3 = ((const uint2*)(g_h1s + (size_t)r3 * HID))[lane];
            float2 a0 = __half22float2(*(__half2*)&u0.x), b0 = __half22float2(*(__half2*)&u0.y);
            float2 a1 = __half22float2(*(__half2*)&u1.x), b1f = __half22float2(*(__half2*)&u1.y);
            float2 a2 = __half22float2(*(__half2*)&u2.x), b2f = __half22float2(*(__half2*)&u2.y);
            float2 a3 = __half22float2(*(__half2*)&u3.x), b3f = __half22float2(*(__half2*)&u3.y);
            v.x += a0.x + a1.x + a2.x + a3.x;
            v.y += a0.y + a1.y + a2.y + a3.y;
            v.z += b0.x + b1f.x + b2f.x + b3f.x;
            v.w += b0.y + b1f.y + b2f.y + b3f.y;
        }
        for (; i < e; ++i) {
            int r0 = __ldcs(g_csr_row + i);
            uint2 u0 = ((const uint2*)(g_h1s + (size_t)r0 * HID))[lane];
            float2 a0 = __half22float2(*(__half2*)&u0.x), b0 = __half22float2(*(__half2*)&u0.y);
            v.x += a0.x; v.y += a0.y; v.z += b0.x; v.w += b0.y;
        }

        float vv[4] = {v.x, v.y, v.z, v.w};
        float hh[4];
        #pragma unroll
        for (int q = 0; q < 4; ++q) {
            hh[q] = fmaf(dn, vv[q], bb[q]);
            sreg[q]  += hh[q];
            sqreg[q] += hh[q] * hh[q];
        }
        uint2 o;
        *(__half2*)&o.x = __floats2half2_rn(hh[0], hh[1]);
        *(__half2*)&o.y = __floats2half2_rn(hh[2], hh[3]);
        __stcs(((uint2*)(g_hpre + (size_t)n * HID)) + lane, o);   // evict-first
    }

    #pragma unroll
    for (int q = 0; q < 4; ++q) {
        atomicAdd(&s_sum[lane * 4 + q], sreg[q]);
        atomicAdd(&s_sq[lane * 4 + q], sqreg[q]);
    }
    __syncthreads();
    if (tid < HID) {
        atomicAdd(&g_sums[tid], s_sum[tid]);
        atomicAdd(&g_sumsq[tid], s_sq[tid]);
    }
}

// ---------------- K8: BN (inline finalize) + relu + 128->2 GEMV -------------
__global__ __launch_bounds__(256) void k_node2(const float* __restrict__ W2,
                                               const float* __restrict__ gamma,
                                               const float* __restrict__ beta) {
    int n = (blockIdx.x * blockDim.x + threadIdx.x) >> 5;
    int lane = threadIdx.x & 31;
    if (n >= N_NODES) return;
    const float inv_n = 1.0f / (float)N_NODES;
    uint2 u = __ldcs(((const uint2*)(g_hpre + (size_t)n * HID)) + lane);
    float2 fa = __half22float2(*(__half2*)&u.x);
    float2 fb = __half22float2(*(__half2*)&u.y);
    float vv[4] = {fa.x, fa.y, fb.x, fb.y};
    float o0 = 0.f, o1 = 0.f;
    #pragma unroll
    for (int q = 0; q < 4; ++q) {
        int j = lane * 4 + q;
        float mu  = __ldg(g_sums + j) * inv_n;
        float var = __ldg(g_sumsq + j) * inv_n - mu * mu;
        float inv = rsqrtf(var + BN_EPS);
        float sc = __ldg(gamma + j) * inv;
        float sh = __ldg(beta + j) - mu * sc;
        float h = fmaf(vv[q], sc, sh);
        h = fmaxf(h, 0.f);
        o0 = fmaf(h, __ldg(W2 + j * 2 + 0), o0);
        o1 = fmaf(h, __ldg(W2 + j * 2 + 1), o1);
    }
    #pragma unroll
    for (int off = 16; off > 0; off >>= 1) {
        o0 += __shfl_xor_sync(0xffffffffu, o0, off);
        o1 += __shfl_xor_sync(0xffffffffu, o1, off);
    }
    if (lane == 0) {
        float d = g_dinv[n];
        g_h2s[n * 2 + 0] = o0 * d;
        g_h2s[n * 2 + 1] = o1 * d;
    }
}

// ---------------- K9: layer-2 aggregation (gather) + bias -------------------
__global__ __launch_bounds__(256) void k_out(const float* __restrict__ b2,
                                             float* __restrict__ out) {
    int n = (blockIdx.x * blockDim.x + threadIdx.x) >> 5;
    int lane = threadIdx.x & 31;
    if (n >= N_NODES) return;
    int s = g_off[n], e = g_off[n + 1];
    float o0 = 0.f, o1 = 0.f;
    for (int i = s + lane; i < e; i += 32) {
        int r = __ldcs(g_csr_row + i);
        float2 v = *(const float2*)(g_h2s + (size_t)r * 2);
        o0 += v.x; o1 += v.y;
    }
    #pragma unroll
    for (int off = 16; off > 0; off >>= 1) {
        o0 += __shfl_xor_sync(0xffffffffu, o0, off);
        o1 += __shfl_xor_sync(0xffffffffu, o1, off);
    }
    if (lane == 0) {
        float d = g_dinv[n];
        float2 self = *(const float2*)(g_h2s + (size_t)n * 2);
        out[n * 2 + 0] = d * (o0 + self.x) + __ldg(b2 + 0);
        out[n * 2 + 1] = d * (o1 + self.y) + __ldg(b2 + 1);
    }
}

// ---------------- launch -----------------------------------------------------
extern "C" void kernel_launch(void* const* d_in, const int* in_sizes, int n_in,
                              void* d_out, int out_size) {
    const float* x  = (const float*)d_in[0];
    const int*   ei = (const int*)d_in[1];
    const float* fi = (const float*)d_in[2];
    const float* W1 = (const float*)d_in[3];
    const float* b1 = (const float*)d_in[4];
    const float* W2 = (const float*)d_in[5];
    const float* b2 = (const float*)d_in[6];
    const float* gm = (const float*)d_in[7];
    const float* bt = (const float*)d_in[8];
    float* out = (float*)d_out;

    k_prep<<<(N_NODES + 255) / 256, 256>>>(W1, fi);                        // 0
    k_deg<<<NBLK_EDGE, 256>>>(ei);                                         // 1
    k_scanf<<<SC_BLOCKS, SC_THREADS>>>();                                  // 2 (dinv ready)
    k_fill<<<NBLK_EDGE, 256>>>(ei);                                        // 3 (ncu slot)
    k_gemm1<<<NBLK_GEMM, 256>>>(x);                                        // 4 (uses dinv)
    k_agg1<<<(N_NODES + 8 * AGG_NPW - 1) / (8 * AGG_NPW), 256>>>(b1);      // 5
    {
        long long tot = (long long)N_NODES * 32;
        k_node2<<<(unsigned)((tot + 255) / 256), 256>>>(W2, gm, bt);       // 6
        k_out<<<(unsigned)((tot + 255) / 256), 256>>>(b2, out);            // 7
    }
}

// round 16
// speedup vs baseline: 1.1220x; 1.0001x over previous
#include <cuda_runtime.h>
#include <cuda_fp16.h>
#include <cstdint>
#include <cstddef>

#define N_NODES 100000
#define N_EDGES 3200000
#define IN_DIM  256
#define HID     128
#define OUT_DIM 2
#define BN_EPS  1e-5f

#define SC_BLOCKS 100
#define SC_THREADS 256
#define SC_PER 4   // 100*256*4 = 102400 >= N_NODES

#define GBM 128
#define GBK 32
#define A_S 36
#define B_S 132
#define NBLK_GEMM ((N_NODES + GBM - 1) / GBM)          // 782
#define NBLK_EDGE ((N_EDGES / 8 + 255) / 256)          // 1563
#define AGG_NPW 4                                       // nodes per warp in agg1

// ---------------- scratch (static device globals; no runtime alloc) --------
__device__ __align__(16) float  g_dinv[N_NODES];
__device__ __align__(16) __half g_h1s[(size_t)N_NODES * HID];   // fp16 dinv[r]*h1
__device__ __align__(16) __half g_hpre[(size_t)N_NODES * HID];  // fp16 pre-BN h
__device__ __align__(16) float  g_h2s[N_NODES * OUT_DIM];
__device__ __align__(16) float  g_W1s[IN_DIM * HID];            // tf32-rounded W1*sig(fi)
__device__ __align__(16) float  g_sums[HID];
__device__ __align__(16) float  g_sumsq[HID];
// CSR by destination
__device__ __align__(16) int    g_cnt[N_NODES];
__device__ __align__(16) int    g_off[N_NODES + 1];
__device__ __align__(16) int    g_rank[N_EDGES];                // edge rank within dest
__device__ __align__(16) int    g_csr_row[N_EDGES];
// fused-scan scratch
__device__ __align__(16) int    g_bpart[SC_BLOCKS];
__device__ int                  g_arrive;

// ---------------- helpers ---------------------------------------------------
__device__ __forceinline__ float to_tf32(float x) {
    uint32_t u;
    asm("cvt.rna.tf32.f32 %0, %1;" : "=r"(u) : "f"(x));
    return __uint_as_float(u);
}

__device__ __forceinline__ void mma_tf32(float* c,
                                         uint32_t a0, uint32_t a1, uint32_t a2, uint32_t a3,
                                         uint32_t b0, uint32_t b1) {
    asm volatile(
        "mma.sync.aligned.m16n8k8.row.col.f32.tf32.tf32.f32 "
        "{%0,%1,%2,%3}, {%4,%5,%6,%7}, {%8,%9}, {%0,%1,%2,%3};"
        : "+f"(c[0]), "+f"(c[1]), "+f"(c[2]), "+f"(c[3])
        : "r"(a0), "r"(a1), "r"(a2), "r"(a3), "r"(b0), "r"(b1));
}

// ---------------- K0: prep (fold sigmoid into W1 -> tf32, zero counters) ----
__global__ void k_prep(const float* __restrict__ W1, const float* __restrict__ fi) {
    int i = blockIdx.x * blockDim.x + threadIdx.x;
    if (i < IN_DIM * HID) {
        int k = i / HID;
        float s = 1.0f / (1.0f + __expf(-fi[k]));
        g_W1s[i] = to_tf32(W1[i] * s);
    }
    if (i < N_NODES) g_cnt[i] = 0;
    if (i < HID) { g_sums[i] = 0.0f; g_sumsq[i] = 0.0f; }
    if (i == 0) g_arrive = 0;
}

// ---------------- K1: in-degree histogram + edge rank ------------------------
__global__ void k_deg(const int* __restrict__ ei) {
    int t = blockIdx.x * blockDim.x + threadIdx.x;
    int e8 = t * 8;
    if (e8 >= N_EDGES) return;
    int4 c0 = *(const int4*)(ei + N_EDGES + e8);
    int4 c1 = *(const int4*)(ei + N_EDGES + e8 + 4);
    int4 k0, k1;
    k0.x = atomicAdd(&g_cnt[c0.x], 1);
    k0.y = atomicAdd(&g_cnt[c0.y], 1);
    k0.z = atomicAdd(&g_cnt[c0.z], 1);
    k0.w = atomicAdd(&g_cnt[c0.w], 1);
    k1.x = atomicAdd(&g_cnt[c1.x], 1);
    k1.y = atomicAdd(&g_cnt[c1.y], 1);
    k1.z = atomicAdd(&g_cnt[c1.z], 1);
    k1.w = atomicAdd(&g_cnt[c1.w], 1);
    *(int4*)(g_rank + e8)     = k0;
    *(int4*)(g_rank + e8 + 4) = k1;
}

// ---------------- K2: FUSED scan (single kernel, device barrier) -------------
__global__ __launch_bounds__(SC_THREADS) void k_scanf() {
    __shared__ int sm[SC_THREADS];
    __shared__ int bp[SC_BLOCKS];
    int t = threadIdx.x, b = blockIdx.x;
    int base = (b * SC_THREADS + t) * SC_PER;
    int cnts[SC_PER];
    int s = 0;
    #pragma unroll
    for (int q = 0; q < SC_PER; ++q) {
        int i = base + q;
        cnts[q] = (i < N_NODES) ? g_cnt[i] : 0;
        s += cnts[q];
    }
    sm[t] = s;
    __syncthreads();
    for (int off = 1; off < SC_THREADS; off <<= 1) {
        int v = (t >= off) ? sm[t - off] : 0;
        __syncthreads();
        sm[t] += v;
        __syncthreads();
    }
    int tpref = sm[t] - s;
    if (t == SC_THREADS - 1) {
        g_bpart[b] = sm[t];
        __threadfence();
        atomicAdd(&g_arrive, 1);
    }
    if (t == 0) {
        while (atomicAdd(&g_arrive, 0) < SC_BLOCKS) { }
    }
    __syncthreads();
    if (t < SC_BLOCKS) bp[t] = g_bpart[t];
    __syncthreads();
    if (t == 0) {
        int run = 0;
        #pragma unroll 4
        for (int i = 0; i < SC_BLOCKS; ++i) { int c = bp[i]; bp[i] = run; run += c; }
    }
    __syncthreads();
    int run = bp[b] + tpref;
    #pragma unroll
    for (int q = 0; q < SC_PER; ++q) {
        int i = base + q;
        if (i < N_NODES) {
            int c = cnts[q];
            g_off[i] = run;
            g_dinv[i] = rsqrtf((float)(c + 1));
            run += c;
            if (i == N_NODES - 1) g_off[N_NODES] = run;
        }
    }
}

// ---------------- K3: fill CSR (atomic-free: pos = off[c] + rank[e]) ---------
__global__ void k_fill(const int* __restrict__ ei) {
    int t = blockIdx.x * blockDim.x + threadIdx.x;
    int e8 = t * 8;
    if (e8 >= N_EDGES) return;
    int4 r0 = *(const int4*)(ei + e8);
    int4 r1 = *(const int4*)(ei + e8 + 4);
    int4 c0 = *(const int4*)(ei + N_EDGES + e8);
    int4 c1 = *(const int4*)(ei + N_EDGES + e8 + 4);
    int4 k0 = *(const int4*)(g_rank + e8);
    int4 k1 = *(const int4*)(g_rank + e8 + 4);
    g_csr_row[g_off[c0.x] + k0.x] = r0.x;
    g_csr_row[g_off[c0.y] + k0.y] = r0.y;
    g_csr_row[g_off[c0.z] + k0.z] = r0.z;
    g_csr_row[g_off[c0.w] + k0.w] = r0.w;
    g_csr_row[g_off[c1.x] + k1.x] = r1.x;
    g_csr_row[g_off[c1.y] + k1.y] = r1.y;
    g_csr_row[g_off[c1.z] + k1.z] = r1.z;
    g_csr_row[g_off[c1.w] + k1.w] = r1.w;
}

// ---------------- K4: tf32 GEMM, reg A-prefetch, dinv-scaled fp16 epilogue --
__global__ __launch_bounds__(256, 2) void k_gemm1(const float* __restrict__ x) {
    __shared__ float As[GBM * A_S];
    __shared__ float Bs[GBK * B_S];
    const int m0   = blockIdx.x * GBM;
    const int tid  = threadIdx.x;
    const int lane = tid & 31;
    const int wid  = tid >> 5;
    const int wm   = wid >> 2;
    const int wn   = wid & 3;
    const int grp  = lane >> 2;
    const int tg   = lane & 3;

    float acc[4][4][4];
    #pragma unroll
    for (int im = 0; im < 4; ++im)
        #pragma unroll
        for (int in = 0; in < 4; ++in)
            #pragma unroll
            for (int q = 0; q < 4; ++q) acc[im][in][q] = 0.f;

    float4 ra[4];

    auto loadA = [&](int k0) {
        #pragma unroll
        for (int p = 0; p < 4; ++p) {
            int slot = tid + p * 256;
            int r = slot >> 3;
            int q = slot & 7;
            int gm = m0 + r;
            ra[p] = make_float4(0.f, 0.f, 0.f, 0.f);
            if (gm < N_NODES)
                ra[p] = *(const float4*)(x + (size_t)gm * IN_DIM + k0 + q * 4);
        }
    };
    auto storeA = [&]() {
        #pragma unroll
        for (int p = 0; p < 4; ++p) {
            int slot = tid + p * 256;
            int r = slot >> 3;
            int q = slot & 7;
            float* dst = As + r * A_S + q * 4;
            dst[0] = to_tf32(ra[p].x);
            dst[1] = to_tf32(ra[p].y);
            dst[2] = to_tf32(ra[p].z);
            dst[3] = to_tf32(ra[p].w);
        }
    };
    auto loadstoreB = [&](int k0) {
        #pragma unroll
        for (int p = 0; p < 4; ++p) {
            int slot = tid + p * 256;
            int r = slot >> 5;
            int c = slot & 31;
            float4 v = *(const float4*)(g_W1s + (size_t)(k0 + r) * HID + c * 4);
            *(float4*)(Bs + r * B_S + c * 4) = v;   // already tf32-rounded
        }
    };

    const int NT = IN_DIM / GBK;   // 8
    loadA(0);
    for (int t = 0; t < NT; ++t) {
        storeA();
        loadstoreB(t * GBK);
        __syncthreads();
        if (t + 1 < NT) loadA((t + 1) * GBK);

        #pragma unroll
        for (int ks = 0; ks < GBK; ks += 8) {
            uint32_t a[4][4], b[4][2];
            #pragma unroll
            for (int im = 0; im < 4; ++im) {
                int mb = wm * 64 + im * 16;
                const float* pa = As + (mb + grp) * A_S + ks + tg;
                a[im][0] = __float_as_uint(pa[0]);
                a[im][1] = __float_as_uint(pa[8 * A_S]);
                a[im][2] = __float_as_uint(pa[4]);
                a[im][3] = __float_as_uint(pa[8 * A_S + 4]);
            }
            #pragma unroll
            for (int in = 0; in < 4; ++in) {
                int nb = wn * 32 + in * 8 + grp;
                const float* pb = Bs + (ks + tg) * B_S + nb;
                b[in][0] = __float_as_uint(pb[0]);
                b[in][1] = __float_as_uint(pb[4 * B_S]);
            }
            #pragma unroll
            for (int im = 0; im < 4; ++im)
                #pragma unroll
                for (int in = 0; in < 4; ++in)
                    mma_tf32(acc[im][in], a[im][0], a[im][1], a[im][2], a[im][3],
                             b[in][0], b[in][1]);
        }
        __syncthreads();
    }

    #pragma unroll
    for (int im = 0; im < 4; ++im) {
        int r0 = m0 + wm * 64 + im * 16 + grp;
        int r1 = r0 + 8;
        float d0 = (r0 < N_NODES) ? g_dinv[r0] : 0.f;
        float d1 = (r1 < N_NODES) ? g_dinv[r1] : 0.f;
        #pragma unroll
        for (int in = 0; in < 4; ++in) {
            int col = wn * 32 + in * 8 + tg * 2;
            if (r0 < N_NODES) {
                __half2 h = __floats2half2_rn(acc[im][in][0] * d0, acc[im][in][1] * d0);
                *(__half2*)(g_h1s + (size_t)r0 * HID + col) = h;
            }
            if (r1 < N_NODES) {
                __half2 h = __floats2half2_rn(acc[im][in][2] * d1, acc[im][in][3] * d1);
                *(__half2*)(g_h1s + (size_t)r1 * HID + col) = h;
            }
        }
    }
}

// ---------------- K5: agg1 — pre-scaled h1 gathers, streaming hints ---------
__global__ __launch_bounds__(256) void k_agg1(const float* __restrict__ b1) {
    __shared__ float s_sum[HID];
    __shared__ float s_sq[HID];
    const int tid  = threadIdx.x;
    const int lane = tid & 31;
    const int warp = tid >> 5;
    if (tid < HID) { s_sum[tid] = 0.f; s_sq[tid] = 0.f; }
    __syncthreads();

    float sreg[4]  = {0.f, 0.f, 0.f, 0.f};
    float sqreg[4] = {0.f, 0.f, 0.f, 0.f};
    const float bb[4] = {__ldg(b1 + lane * 4 + 0), __ldg(b1 + lane * 4 + 1),
                         __ldg(b1 + lane * 4 + 2), __ldg(b1 + lane * 4 + 3)};

    int n0 = (blockIdx.x * 8 + warp) * AGG_NPW;
    #pragma unroll
    for (int k = 0; k < AGG_NPW; ++k) {
        int n = n0 + k;
        if (n >= N_NODES) break;
        int s = g_off[n], e = g_off[n + 1];
        float dn = g_dinv[n];
        float4 v;
        {
            uint2 u = ((const uint2*)(g_h1s + (size_t)n * HID))[lane];
            float2 fa = __half22float2(*(__half2*)&u.x);
            float2 fb = __half22float2(*(__half2*)&u.y);
            v = make_float4(fa.x, fa.y, fb.x, fb.y);
        }
        int i = s;
        for (; i + 4 <= e; i += 4) {
            int r0 = __ldcs(g_csr_row + i);
            int r1 = __ldcs(g_csr_row + i + 1);
            int r2 = __ldcs(g_csr_row + i + 2);
            int r3 = __ldcs(g_csr_row + i + 3);
            uint2 u0 = ((const uint2*)(g_h1s + (size_t)r0 * HID))[lane];
            uint2 u1 = ((const uint2*)(g_h1s + (size_t)r1 * HID))[lane];
            uint2 u2 = ((const uint2*)(g_h1s + (size_t)r2 * HID))[lane];
            uint2 u3 = ((const uint2*)(g_h1s + (size_t)r3 * HID))[lane];
            float2 a0 = __half22float2(*(__half2*)&u0.x), b0 = __half22float2(*(__half2*)&u0.y);
            float2 a1 = __half22float2(*(__half2*)&u1.x), b1f = __half22float2(*(__half2*)&u1.y);
            float2 a2 = __half22float2(*(__half2*)&u2.x), b2f = __half22float2(*(__half2*)&u2.y);
            float2 a3 = __half22float2(*(__half2*)&u3.x), b3f = __half22float2(*(__half2*)&u3.y);
            v.x += a0.x + a1.x + a2.x + a3.x;
            v.y += a0.y + a1.y + a2.y + a3.y;
            v.z += b0.x + b1f.x + b2f.x + b3f.x;
            v.w += b0.y + b1f.y + b2f.y + b3f.y;
        }
        for (; i < e; ++i) {
            int r0 = __ldcs(g_csr_row + i);
            uint2 u0 = ((const uint2*)(g_h1s + (size_t)r0 * HID))[lane];
            float2 a0 = __half22float2(*(__half2*)&u0.x), b0 = __half22float2(*(__half2*)&u0.y);
            v.x += a0.x; v.y += a0.y; v.z += b0.x; v.w += b0.y;
        }

        float vv[4] = {v.x, v.y, v.z, v.w};
        float hh[4];
        #pragma unroll
        for (int q = 0; q < 4; ++q) {
            hh[q] = fmaf(dn, vv[q], bb[q]);
            sreg[q]  += hh[q];
            sqreg[q] += hh[q] * hh[q];
        }
        uint2 o;
        *(__half2*)&o.x = __floats2half2_rn(hh[0], hh[1]);
        *(__half2*)&o.y = __floats2half2_rn(hh[2], hh[3]);
        __stcs(((uint2*)(g_hpre + (size_t)n * HID)) + lane, o);
    }

    #pragma unroll
    for (int q = 0; q < 4; ++q) {
        atomicAdd(&s_sum[lane * 4 + q], sreg[q]);
        atomicAdd(&s_sq[lane * 4 + q], sqreg[q]);
    }
    __syncthreads();
    if (tid < HID) {
        atomicAdd(&g_sums[tid], s_sum[tid]);
        atomicAdd(&g_sumsq[tid], s_sq[tid]);
    }
}

// ---------------- K8: BN (inline finalize) + relu + 128->2 GEMV -------------
__global__ __launch_bounds__(256) void k_node2(const float* __restrict__ W2,
                                               const float* __restrict__ gamma,
                                               const float* __restrict__ beta) {
    int n = (blockIdx.x * blockDim.x + threadIdx.x) >> 5;
    int lane = threadIdx.x & 31;
    if (n >= N_NODES) return;
    const float inv_n = 1.0f / (float)N_NODES;
    uint2 u = __ldcs(((const uint2*)(g_hpre + (size_t)n * HID)) + lane);
    float2 fa = __half22float2(*(__half2*)&u.x);
    float2 fb = __half22float2(*(__half2*)&u.y);
    float vv[4] = {fa.x, fa.y, fb.x, fb.y};
    float o0 = 0.f, o1 = 0.f;
    #pragma unroll
    for (int q = 0; q < 4; ++q) {
        int j = lane * 4 + q;
        float mu  = __ldg(g_sums + j) * inv_n;
        float var = __ldg(g_sumsq + j) * inv_n - mu * mu;
        float inv = rsqrtf(var + BN_EPS);
        float sc = __ldg(gamma + j) * inv;
        float sh = __ldg(beta + j) - mu * sc;
        float h = fmaf(vv[q], sc, sh);
        h = fmaxf(h, 0.f);
        o0 = fmaf(h, __ldg(W2 + j * 2 + 0), o0);
        o1 = fmaf(h, __ldg(W2 + j * 2 + 1), o1);
    }
    #pragma unroll
    for (int off = 16; off > 0; off >>= 1) {
        o0 += __shfl_xor_sync(0xffffffffu, o0, off);
        o1 += __shfl_xor_sync(0xffffffffu, o1, off);
    }
    if (lane == 0) {
        float d = g_dinv[n];
        g_h2s[n * 2 + 0] = o0 * d;
        g_h2s[n * 2 + 1] = o1 * d;
    }
}

// ---------------- K9: layer-2 aggregation (gather) + bias -------------------
__global__ __launch_bounds__(256) void k_out(const float* __restrict__ b2,
                                             float* __restrict__ out) {
    int n = (blockIdx.x * blockDim.x + threadIdx.x) >> 5;
    int lane = threadIdx.x & 31;
    if (n >= N_NODES) return;
    int s = g_off[n], e = g_off[n + 1];
    float o0 = 0.f, o1 = 0.f;
    for (int i = s + lane; i < e; i += 32) {
        int r = __ldcs(g_csr_row + i);
        float2 v = *(const float2*)(g_h2s + (size_t)r * 2);
        o0 += v.x; o1 += v.y;
    }
    #pragma unroll
    for (int off = 16; off > 0; off >>= 1) {
        o0 += __shfl_xor_sync(0xffffffffu, o0, off);
        o1 += __shfl_xor_sync(0xffffffffu, o1, off);
    }
    if (lane == 0) {
        float d = g_dinv[n];
        float2 self = *(const float2*)(g_h2s + (size_t)n * 2);
        out[n * 2 + 0] = d * (o0 + self.x) + __ldg(b2 + 0);
        out[n * 2 + 1] = d * (o1 + self.y) + __ldg(b2 + 1);
    }
}

// ---------------- launch -----------------------------------------------------
extern "C" void kernel_launch(void* const* d_in, const int* in_sizes, int n_in,
                              void* d_out, int out_size) {
    const float* x  = (const float*)d_in[0];
    const int*   ei = (const int*)d_in[1];
    const float* fi = (const float*)d_in[2];
    const float* W1 = (const float*)d_in[3];
    const float* b1 = (const float*)d_in[4];
    const float* W2 = (const float*)d_in[5];
    const float* b2 = (const float*)d_in[6];
    const float* gm = (const float*)d_in[7];
    const float* bt = (const float*)d_in[8];
    float* out = (float*)d_out;

    k_prep<<<(N_NODES + 255) / 256, 256>>>(W1, fi);                        // 0
    k_deg<<<NBLK_EDGE, 256>>>(ei);                                         // 1 (+rank)
    k_scanf<<<SC_BLOCKS, SC_THREADS>>>();                                  // 2
    k_fill<<<NBLK_EDGE, 256>>>(ei);                                        // 3 (ncu, atomic-free)
    k_gemm1<<<NBLK_GEMM, 256>>>(x);                                        // 4
    k_agg1<<<(N_NODES + 8 * AGG_NPW - 1) / (8 * AGG_NPW), 256>>>(b1);      // 5
    {
        long long tot = (long long)N_NODES * 32;
        k_node2<<<(unsigned)((tot + 255) / 256), 256>>>(W2, gm, bt);       // 6
        k_out<<<(unsigned)((tot + 255) / 256), 256>>>(b2, out);            // 7
    }
}